// round 5
// baseline (speedup 1.0000x reference)
#include <cuda_runtime.h>
#include <cstdint>
#include <float.h>

#define NB 2048     // batch
#define NH 50       // history
#define ND 128      // dim (K)
#define NV 100000   // vocab
#define NK 10       // top_k

#define TM 128      // rowtile (batch)
#define TN 64       // coltile (vocab)
#define NCOLT ((NV + TN - 1) / TN)   // 1563
#define NCG 9                        // column groups
#define NRT (NB / TM)                // 16

#define APITCH 132                   // smem pitch in floats

// smem: sA f32 [128][132], sB f32 double [2][64][132]  -> 135168 B
#define SMEM_FLOATS (TM * APITCH + 2 * TN * APITCH)

__device__ float g_ctx[NB * ND];

__device__ __forceinline__ float tf32_rna(float x) {
    uint32_t u;
    asm("cvt.rna.tf32.f32 %0, %1;" : "=r"(u) : "f"(x));
    return __uint_as_float(u);
}

// split f32 -> tf32 hi/lo (register-level, per use)
__device__ __forceinline__ void split(float a, uint32_t& hi, uint32_t& lo) {
    float h = tf32_rna(a);
    hi = __float_as_uint(h);
    lo = __float_as_uint(tf32_rna(a - h));
}

// m16n8k8 tf32 mma, f32 accumulate
__device__ __forceinline__ void mma8(float (&d)[4], const uint32_t (&a)[4], const uint32_t (&b)[2]) {
    asm("mma.sync.aligned.m16n8k8.row.col.f32.tf32.tf32.f32 "
        "{%0,%1,%2,%3}, {%4,%5,%6,%7}, {%8,%9}, {%0,%1,%2,%3};"
        : "+f"(d[0]), "+f"(d[1]), "+f"(d[2]), "+f"(d[3])
        : "r"(a[0]), "r"(a[1]), "r"(a[2]), "r"(a[3]), "r"(b[0]), "r"(b[1]));
}

__device__ __forceinline__ void cp_async16(float* dst, const float* src) {
    uint32_t da = (uint32_t)__cvta_generic_to_shared(dst);
    asm volatile("cp.async.cg.shared.global [%0], [%1], 16;" :: "r"(da), "l"(src));
}
__device__ __forceinline__ void cp_commit() {
    asm volatile("cp.async.commit_group;" ::: "memory");
}
__device__ __forceinline__ void cp_wait0() {
    asm volatile("cp.async.wait_group 0;" ::: "memory");
}
__device__ __forceinline__ void cp_wait1() {
    asm volatile("cp.async.wait_group 1;" ::: "memory");
}

// ---------------------------------------------------------------------------
// Kernel 1: ctx = mean(ctab[ids]) @ W + b  (f32)
// ---------------------------------------------------------------------------
__global__ void ctx_kernel(const int* __restrict__ ids,
                           const float* __restrict__ ctab,
                           const float* __restrict__ W,
                           const float* __restrict__ bias) {
    int r = blockIdx.x;
    int d = threadIdx.x;
    __shared__ float pooled[ND];

    float s = 0.0f;
    #pragma unroll 5
    for (int h = 0; h < NH; ++h) {
        int id = ids[r * NH + h];
        s += ctab[(long)id * ND + d];
    }
    pooled[d] = s * (1.0f / (float)NH);
    __syncthreads();

    float acc = bias[d];
    #pragma unroll 8
    for (int i = 0; i < ND; ++i)
        acc = fmaf(pooled[i], W[i * ND + d], acc);
    g_ctx[r * ND + d] = acc;
}

// ---------------------------------------------------------------------------
// Kernel 2: logits = ctx @ labelT via mma.sync 3xTF32
// f32 in smem; tf32 hi/lo split at frag-load time. cp.async double-buffered B.
// ---------------------------------------------------------------------------
extern __shared__ float sm_g[];

__device__ __forceinline__ void issue_b(const float* __restrict__ label, int ct,
                                        float* sBbuf, int pn, int pd) {
    long gn = (long)ct * TN + pn;
    if (gn > NV - 1) gn = NV - 1;          // clamp (garbage cols discarded at write)
    const float* src = label + gn * ND + pd;
    float* dst = sBbuf + pn * APITCH + pd;
    #pragma unroll
    for (int j = 0; j < 8; ++j)
        cp_async16(dst + j * 16, src + j * 16);
}

__global__ __launch_bounds__(256, 1)
void gemm_kernel(const float* __restrict__ label, float* __restrict__ out) {
    float* sA  = sm_g;
    float* sB0 = sm_g + TM * APITCH;
    float* sB1 = sB0 + TN * APITCH;

    const int tid  = threadIdx.x;
    const int lane = tid & 31;
    const int wid  = tid >> 5;
    const int r0   = blockIdx.y * TM;

    // ---- Load resident A rowtile (f32) ----
    {
        int m  = tid >> 1;
        int d0 = (tid & 1) * 64;
        const float4* src = (const float4*)(g_ctx + (long)(r0 + m) * ND + d0);
        float* dst = sA + m * APITCH + d0;
        #pragma unroll
        for (int j = 0; j < 16; ++j) *(float4*)(dst + j * 4) = src[j];
    }

    const int aRow = (wid >> 1) * 32 + (lane >> 2);
    const int bCol = (wid & 1) * 32 + (lane >> 2);
    const int kq   = lane & 3;
    const int pn   = tid >> 2;
    const int pd   = (tid & 3) * 4;

    // prefetch tile 0 into sB0
    issue_b(label, blockIdx.x, sB0, pn, pd);
    cp_commit();

    int ct = blockIdx.x;
    int cur = 0;
    while (true) {
        const int nct = ct + NCG;
        const bool hasnext = (nct < NCOLT);
        if (hasnext) {
            issue_b(label, nct, cur ? sB0 : sB1, pn, pd);
            cp_commit();
            cp_wait1();
        } else {
            cp_wait0();
        }
        __syncthreads();

        const float* sB = cur ? sB1 : sB0;

        float acc[2][4][4];
        #pragma unroll
        for (int mi = 0; mi < 2; ++mi)
            #pragma unroll
            for (int ni = 0; ni < 4; ++ni)
                #pragma unroll
                for (int q = 0; q < 4; ++q) acc[mi][ni][q] = 0.0f;

        #pragma unroll 4
        for (int k0 = 0; k0 < ND; k0 += 8) {
            uint32_t ah[2][4], al[2][4], bh[4][2], bl[4][2];
            #pragma unroll
            for (int mi = 0; mi < 2; ++mi) {
                const float* pa = sA + (aRow + mi * 16) * APITCH + k0 + kq;
                split(pa[0],              ah[mi][0], al[mi][0]);
                split(pa[8 * APITCH],     ah[mi][1], al[mi][1]);
                split(pa[4],              ah[mi][2], al[mi][2]);
                split(pa[8 * APITCH + 4], ah[mi][3], al[mi][3]);
            }
            #pragma unroll
            for (int ni = 0; ni < 4; ++ni) {
                const float* pb = sB + (bCol + ni * 8) * APITCH + k0 + kq;
                split(pb[0], bh[ni][0], bl[ni][0]);
                split(pb[4], bh[ni][1], bl[ni][1]);
            }
            #pragma unroll
            for (int mi = 0; mi < 2; ++mi)
                #pragma unroll
                for (int ni = 0; ni < 4; ++ni) {
                    mma8(acc[mi][ni], ah[mi], bh[ni]);   // hi*hi
                    mma8(acc[mi][ni], ah[mi], bl[ni]);   // hi*lo
                    mma8(acc[mi][ni], al[mi], bh[ni]);   // lo*hi
                }
        }

        // ---- epilogue: streaming stores ----
        {
            const int n0 = ct * TN;
            #pragma unroll
            for (int mi = 0; mi < 2; ++mi) {
                long rg = r0 + (wid >> 1) * 32 + mi * 16 + (lane >> 2);
                float* o0 = out + rg * (long)NV;
                float* o1 = o0 + 8l * NV;
                #pragma unroll
                for (int ni = 0; ni < 4; ++ni) {
                    int cg = n0 + (wid & 1) * 32 + ni * 8 + 2 * (lane & 3);
                    if (cg < NV) {
                        __stcs((float2*)(o0 + cg), make_float2(acc[mi][ni][0], acc[mi][ni][1]));
                        __stcs((float2*)(o1 + cg), make_float2(acc[mi][ni][2], acc[mi][ni][3]));
                    }
                }
            }
        }
        __syncthreads();   // all reads of this buffer done before it's refilled

        if (!hasnext) break;
        ct = nct;
        cur ^= 1;
    }
}

// ---------------------------------------------------------------------------
// Kernel 3: per-row top-10 (value desc, index asc ties); vector-max prefilter
// ---------------------------------------------------------------------------
#define TKT 512

__device__ __forceinline__ void tk_insert(float v, int id, float (&tv)[NK], int (&ti)[NK]) {
    if (v > tv[NK - 1]) {
        tv[NK - 1] = v; ti[NK - 1] = id;
        #pragma unroll
        for (int j = NK - 1; j > 0; --j) {
            if (tv[j] > tv[j - 1]) {
                float fv = tv[j]; tv[j] = tv[j - 1]; tv[j - 1] = fv;
                int ii = ti[j]; ti[j] = ti[j - 1]; ti[j - 1] = ii;
            }
        }
    }
}

__global__ __launch_bounds__(TKT)
void topk_kernel(const float* __restrict__ logits,
                 float* __restrict__ out_ids,
                 float* __restrict__ out_scores) {
    const int row = blockIdx.x;
    const int tid = threadIdx.x;
    const float4* p = (const float4*)(logits + (long)row * NV);

    float tv[NK]; int ti[NK];
    #pragma unroll
    for (int j = 0; j < NK; ++j) { tv[j] = -FLT_MAX; ti[j] = 0; }

    for (int i = tid; i < NV / 4; i += TKT) {
        float4 v = __ldcs(p + i);
        float m = fmaxf(fmaxf(v.x, v.y), fmaxf(v.z, v.w));
        if (m > tv[NK - 1]) {
            int base = i * 4;
            tk_insert(v.x, base + 0, tv, ti);
            tk_insert(v.y, base + 1, tv, ti);
            tk_insert(v.z, base + 2, tv, ti);
            tk_insert(v.w, base + 3, tv, ti);
        }
    }

    __shared__ float sv[TKT * NK];
    __shared__ int   si[TKT * NK];
    #pragma unroll
    for (int j = 0; j < NK; ++j) { sv[tid * NK + j] = tv[j]; si[tid * NK + j] = ti[j]; }
    __syncthreads();

    for (int s = TKT / 2; s > 0; s >>= 1) {
        if (tid < s) {
            const float* Av = sv + tid * NK;
            const int*   Ai = si + tid * NK;
            const float* Bv = sv + (tid + s) * NK;
            const int*   Bi = si + (tid + s) * NK;
            float mv[NK]; int mi[NK];
            int pa = 0, pb = 0;
            #pragma unroll
            for (int t = 0; t < NK; ++t) {
                float av = Av[pa], bv = Bv[pb];
                int   ai = Ai[pa], bi = Bi[pb];
                bool takeA = (av > bv) || (av == bv && ai < bi);
                if (takeA) { mv[t] = av; mi[t] = ai; ++pa; }
                else       { mv[t] = bv; mi[t] = bi; ++pb; }
            }
            #pragma unroll
            for (int t = 0; t < NK; ++t) { sv[tid * NK + t] = mv[t]; si[tid * NK + t] = mi[t]; }
        }
        __syncthreads();
    }

    if (tid < NK) {
        out_ids[row * NK + tid]    = (float)si[tid];
        out_scores[row * NK + tid] = sv[tid];
    }
}

// ---------------------------------------------------------------------------
// Launch
// ---------------------------------------------------------------------------
extern "C" void kernel_launch(void* const* d_in, const int* in_sizes, int n_in,
                              void* d_out, int out_size) {
    const int*   ids  = (const int*)d_in[0];
    const float* ctab = (const float*)d_in[1];
    const float* ltab = (const float*)d_in[2];
    const float* W    = (const float*)d_in[3];
    const float* bias = (const float*)d_in[4];

    float* out        = (float*)d_out;
    float* logits     = out;
    float* out_ids    = out + (long)NB * NV;
    float* out_scores = out_ids + NB * NK;

    ctx_kernel<<<NB, ND>>>(ids, ctab, W, bias);

    size_t smem = (size_t)SMEM_FLOATS * 4;   // 135168 B
    cudaFuncSetAttribute(gemm_kernel, cudaFuncAttributeMaxDynamicSharedMemorySize, (int)smem);
    dim3 grid(NCG, NRT);
    gemm_kernel<<<grid, 256, smem>>>(ltab, logits);

    topk_kernel<<<NB, TKT>>>(logits, out_ids, out_scores);
}

// round 6
// speedup vs baseline: 1.0762x; 1.0762x over previous
#include <cuda_runtime.h>
#include <cstdint>
#include <float.h>

#define NB 2048     // batch
#define NH 50       // history
#define ND 128      // dim (K)
#define NV 100000   // vocab
#define NK 10       // top_k

#define TM 128      // rowtile (batch)
#define TN 64       // coltile (vocab)
#define NCOLT ((NV + TN - 1) / TN)   // 1563
#define NCG 9                        // column groups
#define NRT (NB / TM)                // 16

#define APITCH 132                   // smem pitch in floats

// smem: A hi [128][132], A lo [128][132], B f32 double [2][64][132] = 202752 B
#define OFF_AHI 0
#define OFF_ALO (TM * APITCH)
#define OFF_B0  (2 * TM * APITCH)
#define OFF_B1  (2 * TM * APITCH + TN * APITCH)
#define SMEM_FLOATS (2 * TM * APITCH + 2 * TN * APITCH)

__device__ float g_ahi[NB * ND];
__device__ float g_alo[NB * ND];

__device__ __forceinline__ float tf32_rna(float x) {
    uint32_t u;
    asm("cvt.rna.tf32.f32 %0, %1;" : "=r"(u) : "f"(x));
    return __uint_as_float(u);
}

__device__ __forceinline__ void split(float a, uint32_t& hi, uint32_t& lo) {
    float h = tf32_rna(a);
    hi = __float_as_uint(h);
    lo = __float_as_uint(tf32_rna(a - h));
}

// m16n8k8 tf32 mma, f32 accumulate
__device__ __forceinline__ void mma8(float (&d)[4], const uint32_t (&a)[4], const uint32_t (&b)[2]) {
    asm("mma.sync.aligned.m16n8k8.row.col.f32.tf32.tf32.f32 "
        "{%0,%1,%2,%3}, {%4,%5,%6,%7}, {%8,%9}, {%0,%1,%2,%3};"
        : "+f"(d[0]), "+f"(d[1]), "+f"(d[2]), "+f"(d[3])
        : "r"(a[0]), "r"(a[1]), "r"(a[2]), "r"(a[3]), "r"(b[0]), "r"(b[1]));
}

__device__ __forceinline__ void cp_async16(float* dst, const float* src) {
    uint32_t da = (uint32_t)__cvta_generic_to_shared(dst);
    asm volatile("cp.async.cg.shared.global [%0], [%1], 16;" :: "r"(da), "l"(src));
}
__device__ __forceinline__ void cp_commit() {
    asm volatile("cp.async.commit_group;" ::: "memory");
}
__device__ __forceinline__ void cp_wait0() {
    asm volatile("cp.async.wait_group 0;" ::: "memory");
}
__device__ __forceinline__ void cp_wait1() {
    asm volatile("cp.async.wait_group 1;" ::: "memory");
}

// ---------------------------------------------------------------------------
// Kernel 1: ctx = mean(ctab[ids]) @ W + b, then tf32 hi/lo split
// ---------------------------------------------------------------------------
__global__ void ctx_kernel(const int* __restrict__ ids,
                           const float* __restrict__ ctab,
                           const float* __restrict__ W,
                           const float* __restrict__ bias) {
    int r = blockIdx.x;
    int d = threadIdx.x;
    __shared__ float pooled[ND];

    float s = 0.0f;
    #pragma unroll 5
    for (int h = 0; h < NH; ++h) {
        int id = ids[r * NH + h];
        s += ctab[(long)id * ND + d];
    }
    pooled[d] = s * (1.0f / (float)NH);
    __syncthreads();

    float acc = bias[d];
    #pragma unroll 8
    for (int i = 0; i < ND; ++i)
        acc = fmaf(pooled[i], W[i * ND + d], acc);

    float hi = tf32_rna(acc);
    float lo = tf32_rna(acc - hi);
    g_ahi[r * ND + d] = hi;
    g_alo[r * ND + d] = lo;
}

// ---------------------------------------------------------------------------
// Kernel 2: logits = ctx @ labelT via mma.sync 3xTF32
// A hi/lo resident in smem (pre-split). B f32 cp.async double-buffered;
// B tf32 split in registers at frag-load time (8 splits/lane/k-step only).
// ---------------------------------------------------------------------------
extern __shared__ float sm_g[];

__device__ __forceinline__ void issue_b(const float* __restrict__ label, int ct,
                                        float* sBbuf, int pn, int pd) {
    long gn = (long)ct * TN + pn;
    if (gn > NV - 1) gn = NV - 1;          // clamp (garbage cols discarded at write)
    const float* src = label + gn * ND + pd;
    float* dst = sBbuf + pn * APITCH + pd;
    #pragma unroll
    for (int j = 0; j < 8; ++j)
        cp_async16(dst + j * 16, src + j * 16);
}

__global__ __launch_bounds__(256, 1)
void gemm_kernel(const float* __restrict__ label, float* __restrict__ out) {
    float* sAhi = sm_g + OFF_AHI;
    float* sAlo = sm_g + OFF_ALO;
    float* sB0  = sm_g + OFF_B0;
    float* sB1  = sm_g + OFF_B1;

    const int tid  = threadIdx.x;
    const int lane = tid & 31;
    const int wid  = tid >> 5;
    const int r0   = blockIdx.y * TM;

    const int pn   = tid >> 2;
    const int pd   = (tid & 3) * 4;

    // prefetch B tile 0 into sB0 (overlaps the A-resident load below)
    issue_b(label, blockIdx.x, sB0, pn, pd);
    cp_commit();

    // ---- Load resident A rowtile (pre-split hi/lo) ----
    {
        int m  = tid >> 1;
        int d0 = (tid & 1) * 64;
        const float4* ph = (const float4*)(g_ahi + (long)(r0 + m) * ND + d0);
        const float4* pl = (const float4*)(g_alo + (long)(r0 + m) * ND + d0);
        float* dh = sAhi + m * APITCH + d0;
        float* dl = sAlo + m * APITCH + d0;
        #pragma unroll
        for (int j = 0; j < 16; ++j) {
            *(float4*)(dh + j * 4) = ph[j];
            *(float4*)(dl + j * 4) = pl[j];
        }
    }

    const int aRow = (wid >> 1) * 32 + (lane >> 2);
    const int bCol = (wid & 1) * 32 + (lane >> 2);
    const int kq   = lane & 3;

    int ct = blockIdx.x;
    int cur = 0;
    while (true) {
        const int nct = ct + NCG;
        const bool hasnext = (nct < NCOLT);
        if (hasnext) {
            issue_b(label, nct, cur ? sB0 : sB1, pn, pd);
            cp_commit();
            cp_wait1();
        } else {
            cp_wait0();
        }
        __syncthreads();

        const float* sB = cur ? sB1 : sB0;

        float acc[2][4][4];
        #pragma unroll
        for (int mi = 0; mi < 2; ++mi)
            #pragma unroll
            for (int ni = 0; ni < 4; ++ni)
                #pragma unroll
                for (int q = 0; q < 4; ++q) acc[mi][ni][q] = 0.0f;

        #pragma unroll 4
        for (int k0 = 0; k0 < ND; k0 += 8) {
            uint32_t ah[2][4], al[2][4], bh[4][2], bl[4][2];
            #pragma unroll
            for (int mi = 0; mi < 2; ++mi) {
                const float* pah = sAhi + (aRow + mi * 16) * APITCH + k0 + kq;
                const float* pal = sAlo + (aRow + mi * 16) * APITCH + k0 + kq;
                ah[mi][0] = __float_as_uint(pah[0]);
                ah[mi][1] = __float_as_uint(pah[8 * APITCH]);
                ah[mi][2] = __float_as_uint(pah[4]);
                ah[mi][3] = __float_as_uint(pah[8 * APITCH + 4]);
                al[mi][0] = __float_as_uint(pal[0]);
                al[mi][1] = __float_as_uint(pal[8 * APITCH]);
                al[mi][2] = __float_as_uint(pal[4]);
                al[mi][3] = __float_as_uint(pal[8 * APITCH + 4]);
            }
            #pragma unroll
            for (int ni = 0; ni < 4; ++ni) {
                const float* pb = sB + (bCol + ni * 8) * APITCH + k0 + kq;
                split(pb[0], bh[ni][0], bl[ni][0]);
                split(pb[4], bh[ni][1], bl[ni][1]);
            }
            #pragma unroll
            for (int mi = 0; mi < 2; ++mi)
                #pragma unroll
                for (int ni = 0; ni < 4; ++ni) {
                    mma8(acc[mi][ni], ah[mi], bh[ni]);   // hi*hi
                    mma8(acc[mi][ni], ah[mi], bl[ni]);   // hi*lo
                    mma8(acc[mi][ni], al[mi], bh[ni]);   // lo*hi
                }
        }

        // ---- epilogue ----
        {
            const int n0 = ct * TN;
            #pragma unroll
            for (int mi = 0; mi < 2; ++mi) {
                long rg = r0 + (wid >> 1) * 32 + mi * 16 + (lane >> 2);
                float* o0 = out + rg * (long)NV;
                float* o1 = o0 + 8l * NV;
                #pragma unroll
                for (int ni = 0; ni < 4; ++ni) {
                    int cg = n0 + (wid & 1) * 32 + ni * 8 + 2 * (lane & 3);
                    if (cg < NV) {
                        *(float2*)(o0 + cg) = make_float2(acc[mi][ni][0], acc[mi][ni][1]);
                        *(float2*)(o1 + cg) = make_float2(acc[mi][ni][2], acc[mi][ni][3]);
                    }
                }
            }
        }
        __syncthreads();   // all reads of current B buffer done before refill

        if (!hasnext) break;
        ct = nct;
        cur ^= 1;
    }
}

// ---------------------------------------------------------------------------
// Kernel 3: per-row top-10 (value desc, index asc ties); vector-max prefilter
// ---------------------------------------------------------------------------
#define TKT 512

__device__ __forceinline__ void tk_insert(float v, int id, float (&tv)[NK], int (&ti)[NK]) {
    if (v > tv[NK - 1]) {
        tv[NK - 1] = v; ti[NK - 1] = id;
        #pragma unroll
        for (int j = NK - 1; j > 0; --j) {
            if (tv[j] > tv[j - 1]) {
                float fv = tv[j]; tv[j] = tv[j - 1]; tv[j - 1] = fv;
                int ii = ti[j]; ti[j] = ti[j - 1]; ti[j - 1] = ii;
            }
        }
    }
}

__global__ __launch_bounds__(TKT)
void topk_kernel(const float* __restrict__ logits,
                 float* __restrict__ out_ids,
                 float* __restrict__ out_scores) {
    const int row = blockIdx.x;
    const int tid = threadIdx.x;
    const float4* p = (const float4*)(logits + (long)row * NV);

    float tv[NK]; int ti[NK];
    #pragma unroll
    for (int j = 0; j < NK; ++j) { tv[j] = -FLT_MAX; ti[j] = 0; }

    for (int i = tid; i < NV / 4; i += TKT) {
        float4 v = p[i];
        float m = fmaxf(fmaxf(v.x, v.y), fmaxf(v.z, v.w));
        if (m > tv[NK - 1]) {
            int base = i * 4;
            tk_insert(v.x, base + 0, tv, ti);
            tk_insert(v.y, base + 1, tv, ti);
            tk_insert(v.z, base + 2, tv, ti);
            tk_insert(v.w, base + 3, tv, ti);
        }
    }

    __shared__ float sv[TKT * NK];
    __shared__ int   si[TKT * NK];
    #pragma unroll
    for (int j = 0; j < NK; ++j) { sv[tid * NK + j] = tv[j]; si[tid * NK + j] = ti[j]; }
    __syncthreads();

    for (int s = TKT / 2; s > 0; s >>= 1) {
        if (tid < s) {
            const float* Av = sv + tid * NK;
            const int*   Ai = si + tid * NK;
            const float* Bv = sv + (tid + s) * NK;
            const int*   Bi = si + (tid + s) * NK;
            float mv[NK]; int mi[NK];
            int pa = 0, pb = 0;
            #pragma unroll
            for (int t = 0; t < NK; ++t) {
                float av = Av[pa], bv = Bv[pb];
                int   ai = Ai[pa], bi = Bi[pb];
                bool takeA = (av > bv) || (av == bv && ai < bi);
                if (takeA) { mv[t] = av; mi[t] = ai; ++pa; }
                else       { mv[t] = bv; mi[t] = bi; ++pb; }
            }
            #pragma unroll
            for (int t = 0; t < NK; ++t) { sv[tid * NK + t] = mv[t]; si[tid * NK + t] = mi[t]; }
        }
        __syncthreads();
    }

    if (tid < NK) {
        out_ids[row * NK + tid]    = (float)si[tid];
        out_scores[row * NK + tid] = sv[tid];
    }
}

// ---------------------------------------------------------------------------
// Launch
// ---------------------------------------------------------------------------
extern "C" void kernel_launch(void* const* d_in, const int* in_sizes, int n_in,
                              void* d_out, int out_size) {
    const int*   ids  = (const int*)d_in[0];
    const float* ctab = (const float*)d_in[1];
    const float* ltab = (const float*)d_in[2];
    const float* W    = (const float*)d_in[3];
    const float* bias = (const float*)d_in[4];

    float* out        = (float*)d_out;
    float* logits     = out;
    float* out_ids    = out + (long)NB * NV;
    float* out_scores = out_ids + NB * NK;

    ctx_kernel<<<NB, ND>>>(ids, ctab, W, bias);

    size_t smem = (size_t)SMEM_FLOATS * 4;   // 202752 B
    cudaFuncSetAttribute(gemm_kernel, cudaFuncAttributeMaxDynamicSharedMemorySize, (int)smem);
    dim3 grid(NCG, NRT);
    gemm_kernel<<<grid, 256, smem>>>(ltab, logits);

    topk_kernel<<<NB, TKT>>>(logits, out_ids, out_scores);
}

// round 7
// speedup vs baseline: 1.1617x; 1.0794x over previous
#include <cuda_runtime.h>
#include <cstdint>
#include <float.h>

#define NB 2048     // batch
#define NH 50       // history
#define ND 128      // dim (K)
#define NV 100000   // vocab
#define NK 10       // top_k

#define TM 128      // rowtile (batch)
#define TN 64       // coltile (vocab)
#define NCOLT ((NV + TN - 1) / TN)   // 1563
#define NCG 9                        // column groups
#define NRT (NB / TM)                // 16

#define APITCH 132                   // smem pitch in floats (132 % 32 == 4: conflict-free)

// smem: A hi [128][132], A lo, B hi [64][132], B lo  = 202752 B
#define OFF_AHI 0
#define OFF_ALO (TM * APITCH)
#define OFF_BHI (2 * TM * APITCH)
#define OFF_BLO (2 * TM * APITCH + TN * APITCH)
#define SMEM_FLOATS (2 * TM * APITCH + 2 * TN * APITCH)

__device__ float g_ahi[NB * ND];
__device__ float g_alo[NB * ND];

__device__ __forceinline__ float tf32_rna(float x) {
    uint32_t u;
    asm("cvt.rna.tf32.f32 %0, %1;" : "=r"(u) : "f"(x));
    return __uint_as_float(u);
}

// m16n8k8 tf32 mma, f32 accumulate
__device__ __forceinline__ void mma8(float (&d)[4], const uint32_t (&a)[4],
                                     uint32_t b0, uint32_t b1) {
    asm("mma.sync.aligned.m16n8k8.row.col.f32.tf32.tf32.f32 "
        "{%0,%1,%2,%3}, {%4,%5,%6,%7}, {%8,%9}, {%0,%1,%2,%3};"
        : "+f"(d[0]), "+f"(d[1]), "+f"(d[2]), "+f"(d[3])
        : "r"(a[0]), "r"(a[1]), "r"(a[2]), "r"(a[3]), "r"(b0), "r"(b1));
}

__device__ __forceinline__ void ldsm4(uint32_t (&r)[4], uint32_t addr) {
    asm volatile("ldmatrix.sync.aligned.m8n8.x4.shared.b16 {%0,%1,%2,%3}, [%4];"
        : "=r"(r[0]), "=r"(r[1]), "=r"(r[2]), "=r"(r[3]) : "r"(addr));
}

// ---------------------------------------------------------------------------
// Kernel 1: ctx = mean(ctab[ids]) @ W + b, then tf32 hi/lo split
// ---------------------------------------------------------------------------
__global__ void ctx_kernel(const int* __restrict__ ids,
                           const float* __restrict__ ctab,
                           const float* __restrict__ W,
                           const float* __restrict__ bias) {
    int r = blockIdx.x;
    int d = threadIdx.x;
    __shared__ float pooled[ND];

    float s = 0.0f;
    #pragma unroll 5
    for (int h = 0; h < NH; ++h) {
        int id = ids[r * NH + h];
        s += ctab[(long)id * ND + d];
    }
    pooled[d] = s * (1.0f / (float)NH);
    __syncthreads();

    float acc = bias[d];
    #pragma unroll 8
    for (int i = 0; i < ND; ++i)
        acc = fmaf(pooled[i], W[i * ND + d], acc);

    float hi = tf32_rna(acc);
    float lo = tf32_rna(acc - hi);
    g_ahi[r * ND + d] = hi;
    g_alo[r * ND + d] = lo;
}

// ---------------------------------------------------------------------------
// Kernel 2: logits = ctx @ labelT via mma.sync 3xTF32
// A & B hi/lo pre-split in smem (R4 structure). ldmatrix frag loads +
// register double-buffered fragments across k-steps.
// ---------------------------------------------------------------------------
extern __shared__ float sm_g[];

__global__ __launch_bounds__(256, 1)
void gemm_kernel(const float* __restrict__ label, float* __restrict__ out) {
    float* sAhi = sm_g + OFF_AHI;
    float* sAlo = sm_g + OFF_ALO;
    float* sBhi = sm_g + OFF_BHI;
    float* sBlo = sm_g + OFF_BLO;

    const int tid  = threadIdx.x;
    const int lane = tid & 31;
    const int wid  = tid >> 5;
    const int r0   = blockIdx.y * TM;

    // ---- Load resident A rowtile (pre-split hi/lo) ----
    {
        int m  = tid >> 1;
        int d0 = (tid & 1) * 64;
        const float4* ph = (const float4*)(g_ahi + (long)(r0 + m) * ND + d0);
        const float4* pl = (const float4*)(g_alo + (long)(r0 + m) * ND + d0);
        float* dh = sAhi + m * APITCH + d0;
        float* dl = sAlo + m * APITCH + d0;
        #pragma unroll
        for (int j = 0; j < 16; ++j) {
            *(float4*)(dh + j * 4) = ph[j];
            *(float4*)(dl + j * 4) = pl[j];
        }
    }

    // ---- Precompute per-thread ldmatrix base addresses (byte, shared space) ----
    const uint32_t sbase = (uint32_t)__cvta_generic_to_shared(sm_g);
    const int jj = lane >> 3, rr = lane & 7;
    uint32_t aH[2], aL[2], bH[2], bL[2];
    {
        // A x4: matrices (m0-7,k0-3)(m8-15,k0-3)(m0-7,k4-7)(m8-15,k4-7)
        int arow = (wid >> 1) * 32 + ((jj & 1) << 3) + rr;
        int akc  = (jj >> 1) << 2;
        #pragma unroll
        for (int mi = 0; mi < 2; ++mi) {
            uint32_t w = (uint32_t)((arow + mi * 16) * APITCH + akc);
            aH[mi] = sbase + (OFF_AHI + w) * 4u;
            aL[mi] = sbase + (OFF_ALO + w) * 4u;
        }
        // B x4 (ni pair): (n0-7,k0-3)(n0-7,k4-7)(n8-15,k0-3)(n8-15,k4-7)
        int brow = (wid & 1) * 32 + ((jj >> 1) << 3) + rr;
        int bkc  = (jj & 1) << 2;
        #pragma unroll
        for (int p = 0; p < 2; ++p) {
            uint32_t w = (uint32_t)((brow + p * 16) * APITCH + bkc);
            bH[p] = sbase + (OFF_BHI + w) * 4u;
            bL[p] = sbase + (OFF_BLO + w) * 4u;
        }
    }

    // B prefetch mapping: thread covers vocab-row pn, words pd + 16j
    const int pn = tid >> 2;
    const int pd = (tid & 3) * 4;
    float4 pf[8];
    {
        int gn = blockIdx.x * TN + pn;
        if (gn < NV) {
            const float4* src = (const float4*)(label + (long)gn * ND + pd);
            #pragma unroll
            for (int j = 0; j < 8; ++j) pf[j] = src[j * 4];
        } else {
            #pragma unroll
            for (int j = 0; j < 8; ++j) pf[j] = make_float4(0.f, 0.f, 0.f, 0.f);
        }
    }

    int ct = blockIdx.x;
    while (true) {
        // ---- fill: split prefetched B into hi/lo smem ----
        __syncthreads();   // prior tile's frag reads done / A resident ready
        {
            float* bh = sBhi + pn * APITCH + pd;
            float* bl = sBlo + pn * APITCH + pd;
            #pragma unroll
            for (int j = 0; j < 8; ++j) {
                float4 v = pf[j];
                float4 h, l;
                h.x = tf32_rna(v.x); l.x = tf32_rna(v.x - h.x);
                h.y = tf32_rna(v.y); l.y = tf32_rna(v.y - h.y);
                h.z = tf32_rna(v.z); l.z = tf32_rna(v.z - h.z);
                h.w = tf32_rna(v.w); l.w = tf32_rna(v.w - h.w);
                *(float4*)(bh + j * 16) = h;
                *(float4*)(bl + j * 16) = l;
            }
        }
        __syncthreads();

        // ---- prefetch next tile into regs (hidden under compute) ----
        const int nct = ct + NCG;
        const bool hasnext = (nct < NCOLT);
        if (hasnext) {
            int gn = nct * TN + pn;
            if (gn < NV) {
                const float4* src = (const float4*)(label + (long)gn * ND + pd);
                #pragma unroll
                for (int j = 0; j < 8; ++j) pf[j] = src[j * 4];
            } else {
                #pragma unroll
                for (int j = 0; j < 8; ++j) pf[j] = make_float4(0.f, 0.f, 0.f, 0.f);
            }
        }

        // ---- compute: register-double-buffered frags, ldmatrix loads ----
        uint32_t AHf[2][2][4], ALf[2][2][4], BHf[2][2][4], BLf[2][2][4];
        float acc[2][4][4];
        #pragma unroll
        for (int mi = 0; mi < 2; ++mi)
            #pragma unroll
            for (int ni = 0; ni < 4; ++ni)
                #pragma unroll
                for (int q = 0; q < 4; ++q) acc[mi][ni][q] = 0.0f;

        // load k-step 0 frags
        ldsm4(AHf[0][0], aH[0]); ldsm4(AHf[0][1], aH[1]);
        ldsm4(ALf[0][0], aL[0]); ldsm4(ALf[0][1], aL[1]);
        ldsm4(BHf[0][0], bH[0]); ldsm4(BHf[0][1], bH[1]);
        ldsm4(BLf[0][0], bL[0]); ldsm4(BLf[0][1], bL[1]);

        #pragma unroll
        for (int ks = 0; ks < 16; ++ks) {
            const int cur = ks & 1;
            if (ks < 15) {
                const int nxt = cur ^ 1;
                const uint32_t ko = (uint32_t)(ks + 1) * 32u;   // 8 floats = 32 B
                ldsm4(AHf[nxt][0], aH[0] + ko); ldsm4(AHf[nxt][1], aH[1] + ko);
                ldsm4(ALf[nxt][0], aL[0] + ko); ldsm4(ALf[nxt][1], aL[1] + ko);
                ldsm4(BHf[nxt][0], bH[0] + ko); ldsm4(BHf[nxt][1], bH[1] + ko);
                ldsm4(BLf[nxt][0], bL[0] + ko); ldsm4(BLf[nxt][1], bL[1] + ko);
            }
            #pragma unroll
            for (int mi = 0; mi < 2; ++mi)
                #pragma unroll
                for (int p = 0; p < 2; ++p) {
                    mma8(acc[mi][2*p],   AHf[cur][mi], BHf[cur][p][0], BHf[cur][p][1]);
                    mma8(acc[mi][2*p+1], AHf[cur][mi], BHf[cur][p][2], BHf[cur][p][3]);
                    mma8(acc[mi][2*p],   AHf[cur][mi], BLf[cur][p][0], BLf[cur][p][1]);
                    mma8(acc[mi][2*p+1], AHf[cur][mi], BLf[cur][p][2], BLf[cur][p][3]);
                    mma8(acc[mi][2*p],   ALf[cur][mi], BHf[cur][p][0], BHf[cur][p][1]);
                    mma8(acc[mi][2*p+1], ALf[cur][mi], BHf[cur][p][2], BHf[cur][p][3]);
                }
        }

        // ---- epilogue ----
        {
            const int n0 = ct * TN;
            #pragma unroll
            for (int mi = 0; mi < 2; ++mi) {
                long rg = r0 + (wid >> 1) * 32 + mi * 16 + (lane >> 2);
                float* o0 = out + rg * (long)NV;
                float* o1 = o0 + 8l * NV;
                #pragma unroll
                for (int ni = 0; ni < 4; ++ni) {
                    int cg = n0 + (wid & 1) * 32 + ni * 8 + 2 * (lane & 3);
                    if (cg < NV) {
                        *(float2*)(o0 + cg) = make_float2(acc[mi][ni][0], acc[mi][ni][1]);
                        *(float2*)(o1 + cg) = make_float2(acc[mi][ni][2], acc[mi][ni][3]);
                    }
                }
            }
        }

        if (!hasnext) break;
        ct = nct;
    }
}

// ---------------------------------------------------------------------------
// Kernel 3: per-row top-10 (value desc, index asc ties); vector-max prefilter
// ---------------------------------------------------------------------------
#define TKT 512

__device__ __forceinline__ void tk_insert(float v, int id, float (&tv)[NK], int (&ti)[NK]) {
    if (v > tv[NK - 1]) {
        tv[NK - 1] = v; ti[NK - 1] = id;
        #pragma unroll
        for (int j = NK - 1; j > 0; --j) {
            if (tv[j] > tv[j - 1]) {
                float fv = tv[j]; tv[j] = tv[j - 1]; tv[j - 1] = fv;
                int ii = ti[j]; ti[j] = ti[j - 1]; ti[j - 1] = ii;
            }
        }
    }
}

__global__ __launch_bounds__(TKT)
void topk_kernel(const float* __restrict__ logits,
                 float* __restrict__ out_ids,
                 float* __restrict__ out_scores) {
    const int row = blockIdx.x;
    const int tid = threadIdx.x;
    const float4* p = (const float4*)(logits + (long)row * NV);

    float tv[NK]; int ti[NK];
    #pragma unroll
    for (int j = 0; j < NK; ++j) { tv[j] = -FLT_MAX; ti[j] = 0; }

    for (int i = tid; i < NV / 4; i += TKT) {
        float4 v = p[i];
        float m = fmaxf(fmaxf(v.x, v.y), fmaxf(v.z, v.w));
        if (m > tv[NK - 1]) {
            int base = i * 4;
            tk_insert(v.x, base + 0, tv, ti);
            tk_insert(v.y, base + 1, tv, ti);
            tk_insert(v.z, base + 2, tv, ti);
            tk_insert(v.w, base + 3, tv, ti);
        }
    }

    __shared__ float sv[TKT * NK];
    __shared__ int   si[TKT * NK];
    #pragma unroll
    for (int j = 0; j < NK; ++j) { sv[tid * NK + j] = tv[j]; si[tid * NK + j] = ti[j]; }
    __syncthreads();

    for (int s = TKT / 2; s > 0; s >>= 1) {
        if (tid < s) {
            const float* Av = sv + tid * NK;
            const int*   Ai = si + tid * NK;
            const float* Bv = sv + (tid + s) * NK;
            const int*   Bi = si + (tid + s) * NK;
            float mv[NK]; int mi[NK];
            int pa = 0, pb = 0;
            #pragma unroll
            for (int t = 0; t < NK; ++t) {
                float av = Av[pa], bv = Bv[pb];
                int   ai = Ai[pa], bi = Bi[pb];
                bool takeA = (av > bv) || (av == bv && ai < bi);
                if (takeA) { mv[t] = av; mi[t] = ai; ++pa; }
                else       { mv[t] = bv; mi[t] = bi; ++pb; }
            }
            #pragma unroll
            for (int t = 0; t < NK; ++t) { sv[tid * NK + t] = mv[t]; si[tid * NK + t] = mi[t]; }
        }
        __syncthreads();
    }

    if (tid < NK) {
        out_ids[row * NK + tid]    = (float)si[tid];
        out_scores[row * NK + tid] = sv[tid];
    }
}

// ---------------------------------------------------------------------------
// Launch
// ---------------------------------------------------------------------------
extern "C" void kernel_launch(void* const* d_in, const int* in_sizes, int n_in,
                              void* d_out, int out_size) {
    const int*   ids  = (const int*)d_in[0];
    const float* ctab = (const float*)d_in[1];
    const float* ltab = (const float*)d_in[2];
    const float* W    = (const float*)d_in[3];
    const float* bias = (const float*)d_in[4];

    float* out        = (float*)d_out;
    float* logits     = out;
    float* out_ids    = out + (long)NB * NV;
    float* out_scores = out_ids + NB * NK;

    ctx_kernel<<<NB, ND>>>(ids, ctab, W, bias);

    size_t smem = (size_t)SMEM_FLOATS * 4;   // 202752 B
    cudaFuncSetAttribute(gemm_kernel, cudaFuncAttributeMaxDynamicSharedMemorySize, (int)smem);
    dim3 grid(NCG, NRT);
    gemm_kernel<<<grid, 256, smem>>>(ltab, logits);

    topk_kernel<<<NB, TKT>>>(logits, out_ids, out_scores);
}

// round 9
// speedup vs baseline: 1.5071x; 1.2973x over previous
#include <cuda_runtime.h>
#include <cuda_fp16.h>
#include <cstdint>
#include <float.h>

#define NB 2048     // batch
#define NH 50       // history
#define ND 128      // dim (K)
#define NV 100000   // vocab
#define NK 10       // top_k

#define TM 128      // rowtile (batch)
#define TN 64       // coltile (vocab)
#define NCOLT ((NV + TN - 1) / TN)   // 1563
#define NCG 9                        // column groups
#define NRT (NB / TM)                // 16

#define SC   1024.0f                 // fp16 scale (exact power of 2)
#define ISC2 (1.0f / (1024.0f * 1024.0f))

#define HPITCH 136                   // smem pitch in halves (272 B rows: LDSM conflict-free)

// smem (half units): A1 [128][136], A2, B1 [64][136], B2  = 104448 B
#define OFF_A1 0
#define OFF_A2 (TM * HPITCH)
#define OFF_B1 (2 * TM * HPITCH)
#define OFF_B2 (2 * TM * HPITCH + TN * HPITCH)
#define SMEM_HALVES (2 * TM * HPITCH + 2 * TN * HPITCH)

__device__ __align__(16) __half g_a1[NB * ND];
__device__ __align__(16) __half g_a2[NB * ND];

// m16n8k16 f16 mma, f32 accumulate (sm_80+ base-target instruction)
__device__ __forceinline__ void mma16(float (&d)[4], const uint32_t (&a)[4],
                                      uint32_t b0, uint32_t b1) {
    asm("mma.sync.aligned.m16n8k16.row.col.f32.f16.f16.f32 "
        "{%0,%1,%2,%3}, {%4,%5,%6,%7}, {%8,%9}, {%0,%1,%2,%3};"
        : "+f"(d[0]), "+f"(d[1]), "+f"(d[2]), "+f"(d[3])
        : "r"(a[0]), "r"(a[1]), "r"(a[2]), "r"(a[3]), "r"(b0), "r"(b1));
}

__device__ __forceinline__ void ldsm4(uint32_t (&r)[4], uint32_t addr) {
    asm volatile("ldmatrix.sync.aligned.m8n8.x4.shared.b16 {%0,%1,%2,%3}, [%4];"
        : "=r"(r[0]), "=r"(r[1]), "=r"(r[2]), "=r"(r[3]) : "r"(addr));
}

// split scaled f32 into two fp16 (a ~= h1 + h2, both normal-range after SC scaling)
__device__ __forceinline__ void hsplit(float a, __half& h1, __half& h2) {
    float w = a * SC;
    h1 = __float2half_rn(w);
    h2 = __float2half_rn(w - __half2float(h1));
}

// ---------------------------------------------------------------------------
// Kernel 1: ctx = mean(ctab[ids]) @ W + b, then scaled fp16 hi/lo split
// ---------------------------------------------------------------------------
__global__ void ctx_kernel(const int* __restrict__ ids,
                           const float* __restrict__ ctab,
                           const float* __restrict__ W,
                           const float* __restrict__ bias) {
    int row = blockIdx.x;
    int d = threadIdx.x;
    __shared__ float pooled[ND];

    float s = 0.0f;
    #pragma unroll 5
    for (int h = 0; h < NH; ++h) {
        int id = ids[row * NH + h];
        s += ctab[(long)id * ND + d];
    }
    pooled[d] = s * (1.0f / (float)NH);
    __syncthreads();

    float acc = bias[d];
    #pragma unroll 8
    for (int i = 0; i < ND; ++i)
        acc = fmaf(pooled[i], W[i * ND + d], acc);

    __half h1, h2;
    hsplit(acc, h1, h2);
    g_a1[row * ND + d] = h1;
    g_a2[row * ND + d] = h2;
}

// ---------------------------------------------------------------------------
// Kernel 2: logits = ctx @ labelT via mma.sync 3x FP16 (2-term split, scaled)
// A parts resident in smem; B f32 register-prefetched, split into smem fp16.
// ldmatrix frag loads + register double-buffered fragments across k16-steps.
// ---------------------------------------------------------------------------
extern __shared__ __half sm_h[];

__global__ __launch_bounds__(256, 1)
void gemm_kernel(const float* __restrict__ label, float* __restrict__ out) {
    const int tid  = threadIdx.x;
    const int lane = tid & 31;
    const int wid  = tid >> 5;
    const int r0   = blockIdx.y * TM;

    // ---- Load resident A rowtile (pre-split fp16 a1/a2) ----
    {
        int m  = tid >> 1;
        int d0 = (tid & 1) * 64;
        const uint4* p1 = (const uint4*)(g_a1 + (long)(r0 + m) * ND + d0);
        const uint4* p2 = (const uint4*)(g_a2 + (long)(r0 + m) * ND + d0);
        uint4* d1 = (uint4*)(sm_h + OFF_A1 + m * HPITCH + d0);
        uint4* d2 = (uint4*)(sm_h + OFF_A2 + m * HPITCH + d0);
        #pragma unroll
        for (int j = 0; j < 8; ++j) { d1[j] = p1[j]; d2[j] = p2[j]; }
    }

    // ---- Precompute per-thread ldmatrix base addresses (bytes) ----
    const uint32_t sbase = (uint32_t)__cvta_generic_to_shared(sm_h);
    uint32_t aA1[2], aA2[2], bB1[2], bB2[2];
    {
        // A x4 (m16n8k16): matrix j: m = base + (j&1)*8 + (t&7), k = (j>>1)*8
        int jrowA = ((lane >> 3) & 1) * 8 + (lane & 7);
        int kcolA = (lane >> 4) * 8;
        #pragma unroll
        for (int mi = 0; mi < 2; ++mi) {
            int rowA = (wid >> 1) * 32 + mi * 16 + jrowA;
            aA1[mi] = sbase + (uint32_t)(OFF_A1 + rowA * HPITCH + kcolA) * 2u;
            aA2[mi] = sbase + (uint32_t)(OFF_A2 + rowA * HPITCH + kcolA) * 2u;
        }
        // B x4: matrix j: n = base + (j>>1)*8 + (t&7), k = (j&1)*8
        int jrowB = (lane >> 4) * 8 + (lane & 7);
        int kcolB = ((lane >> 3) & 1) * 8;
        #pragma unroll
        for (int p = 0; p < 2; ++p) {
            int rowB = (wid & 1) * 32 + p * 16 + jrowB;
            bB1[p] = sbase + (uint32_t)(OFF_B1 + rowB * HPITCH + kcolB) * 2u;
            bB2[p] = sbase + (uint32_t)(OFF_B2 + rowB * HPITCH + kcolB) * 2u;
        }
    }

    // B prefetch mapping: thread covers vocab-row pn, float-cols pd + 16j
    const int pn = tid >> 2;
    const int pd = (tid & 3) * 4;
    float4 pf[8];
    {
        int gn = blockIdx.x * TN + pn;
        if (gn < NV) {
            const float4* src = (const float4*)(label + (long)gn * ND + pd);
            #pragma unroll
            for (int j = 0; j < 8; ++j) pf[j] = src[j * 4];
        } else {
            #pragma unroll
            for (int j = 0; j < 8; ++j) pf[j] = make_float4(0.f, 0.f, 0.f, 0.f);
        }
    }

    int ct = blockIdx.x;
    while (true) {
        // ---- fill: split prefetched B into fp16 b1/b2 smem ----
        __syncthreads();   // prior tile's frag reads done / A resident ready
        {
            __half* b1 = sm_h + OFF_B1 + pn * HPITCH + pd;
            __half* b2 = sm_h + OFF_B2 + pn * HPITCH + pd;
            #pragma unroll
            for (int j = 0; j < 8; ++j) {
                float4 v = pf[j];
                __half hx1, hx2, hy1, hy2, hz1, hz2, hw1, hw2;
                hsplit(v.x, hx1, hx2); hsplit(v.y, hy1, hy2);
                hsplit(v.z, hz1, hz2); hsplit(v.w, hw1, hw2);
                __half2* q1 = (__half2*)(b1 + j * 16);
                __half2* q2 = (__half2*)(b2 + j * 16);
                q1[0] = __halves2half2(hx1, hy1);
                q1[1] = __halves2half2(hz1, hw1);
                q2[0] = __halves2half2(hx2, hy2);
                q2[1] = __halves2half2(hz2, hw2);
            }
        }
        __syncthreads();

        // ---- prefetch next tile into regs (hidden under compute) ----
        const int nct = ct + NCG;
        const bool hasnext = (nct < NCOLT);
        if (hasnext) {
            int gn = nct * TN + pn;
            if (gn < NV) {
                const float4* src = (const float4*)(label + (long)gn * ND + pd);
                #pragma unroll
                for (int j = 0; j < 8; ++j) pf[j] = src[j * 4];
            } else {
                #pragma unroll
                for (int j = 0; j < 8; ++j) pf[j] = make_float4(0.f, 0.f, 0.f, 0.f);
            }
        }

        // ---- compute: register-double-buffered frags, ldmatrix loads ----
        uint32_t A1f[2][2][4], A2f[2][2][4], B1f[2][2][4], B2f[2][2][4];
        float acc[2][4][4];
        #pragma unroll
        for (int mi = 0; mi < 2; ++mi)
            #pragma unroll
            for (int ni = 0; ni < 4; ++ni)
                #pragma unroll
                for (int q = 0; q < 4; ++q) acc[mi][ni][q] = 0.0f;

        // load k-step 0 frags
        ldsm4(A1f[0][0], aA1[0]); ldsm4(A1f[0][1], aA1[1]);
        ldsm4(A2f[0][0], aA2[0]); ldsm4(A2f[0][1], aA2[1]);
        ldsm4(B1f[0][0], bB1[0]); ldsm4(B1f[0][1], bB1[1]);
        ldsm4(B2f[0][0], bB2[0]); ldsm4(B2f[0][1], bB2[1]);

        #pragma unroll
        for (int ks = 0; ks < 8; ++ks) {           // k16 steps: 8 * 16 = 128
            const int cur = ks & 1;
            if (ks < 7) {
                const int nxt = cur ^ 1;
                const uint32_t ko = (uint32_t)(ks + 1) * 32u;   // 16 halves = 32 B
                ldsm4(A1f[nxt][0], aA1[0] + ko); ldsm4(A1f[nxt][1], aA1[1] + ko);
                ldsm4(A2f[nxt][0], aA2[0] + ko); ldsm4(A2f[nxt][1], aA2[1] + ko);
                ldsm4(B1f[nxt][0], bB1[0] + ko); ldsm4(B1f[nxt][1], bB1[1] + ko);
                ldsm4(B2f[nxt][0], bB2[0] + ko); ldsm4(B2f[nxt][1], bB2[1] + ko);
            }
            #pragma unroll
            for (int mi = 0; mi < 2; ++mi)
                #pragma unroll
                for (int p = 0; p < 2; ++p) {
                    // frag(ni=2p) = {r0,r1}, frag(ni=2p+1) = {r2,r3}
                    mma16(acc[mi][2*p],   A1f[cur][mi], B1f[cur][p][0], B1f[cur][p][1]);
                    mma16(acc[mi][2*p+1], A1f[cur][mi], B1f[cur][p][2], B1f[cur][p][3]);
                    mma16(acc[mi][2*p],   A1f[cur][mi], B2f[cur][p][0], B2f[cur][p][1]);
                    mma16(acc[mi][2*p+1], A1f[cur][mi], B2f[cur][p][2], B2f[cur][p][3]);
                    mma16(acc[mi][2*p],   A2f[cur][mi], B1f[cur][p][0], B1f[cur][p][1]);
                    mma16(acc[mi][2*p+1], A2f[cur][mi], B1f[cur][p][2], B1f[cur][p][3]);
                }
        }

        // ---- epilogue: un-scale by exact 2^-20 and store ----
        {
            const int n0 = ct * TN;
            #pragma unroll
            for (int mi = 0; mi < 2; ++mi) {
                long rg = r0 + (wid >> 1) * 32 + mi * 16 + (lane >> 2);
                float* o0 = out + rg * (long)NV;
                float* o1 = o0 + 8l * NV;
                #pragma unroll
                for (int ni = 0; ni < 4; ++ni) {
                    int cg = n0 + (wid & 1) * 32 + ni * 8 + 2 * (lane & 3);
                    if (cg < NV) {
                        *(float2*)(o0 + cg) = make_float2(acc[mi][ni][0] * ISC2,
                                                          acc[mi][ni][1] * ISC2);
                        *(float2*)(o1 + cg) = make_float2(acc[mi][ni][2] * ISC2,
                                                          acc[mi][ni][3] * ISC2);
                    }
                }
            }
        }

        if (!hasnext) break;
        ct = nct;
    }
}

// ---------------------------------------------------------------------------
// Kernel 3: per-row top-10 (value desc, index asc ties); vector-max prefilter
// ---------------------------------------------------------------------------
#define TKT 512

__device__ __forceinline__ void tk_insert(float v, int id, float (&tv)[NK], int (&ti)[NK]) {
    if (v > tv[NK - 1]) {
        tv[NK - 1] = v; ti[NK - 1] = id;
        #pragma unroll
        for (int j = NK - 1; j > 0; --j) {
            if (tv[j] > tv[j - 1]) {
                float fv = tv[j]; tv[j] = tv[j - 1]; tv[j - 1] = fv;
                int ii = ti[j]; ti[j] = ti[j - 1]; ti[j - 1] = ii;
            }
        }
    }
}

__global__ __launch_bounds__(TKT)
void topk_kernel(const float* __restrict__ logits,
                 float* __restrict__ out_ids,
                 float* __restrict__ out_scores) {
    const int row = blockIdx.x;
    const int tid = threadIdx.x;
    const float4* p = (const float4*)(logits + (long)row * NV);

    float tv[NK]; int ti[NK];
    #pragma unroll
    for (int j = 0; j < NK; ++j) { tv[j] = -FLT_MAX; ti[j] = 0; }

    for (int i = tid; i < NV / 4; i += TKT) {
        float4 v = p[i];
        float m = fmaxf(fmaxf(v.x, v.y), fmaxf(v.z, v.w));
        if (m > tv[NK - 1]) {
            int base = i * 4;
            tk_insert(v.x, base + 0, tv, ti);
            tk_insert(v.y, base + 1, tv, ti);
            tk_insert(v.z, base + 2, tv, ti);
            tk_insert(v.w, base + 3, tv, ti);
        }
    }

    __shared__ float sv[TKT * NK];
    __shared__ int   si[TKT * NK];
    #pragma unroll
    for (int j = 0; j < NK; ++j) { sv[tid * NK + j] = tv[j]; si[tid * NK + j] = ti[j]; }
    __syncthreads();

    for (int s = TKT / 2; s > 0; s >>= 1) {
        if (tid < s) {
            const float* Av = sv + tid * NK;
            const int*   Ai = si + tid * NK;
            const float* Bv = sv + (tid + s) * NK;
            const int*   Bi = si + (tid + s) * NK;
            float mv[NK]; int mi[NK];
            int pa = 0, pb = 0;
            #pragma unroll
            for (int t = 0; t < NK; ++t) {
                float av = Av[pa], bv = Bv[pb];
                int   ai = Ai[pa], bi = Bi[pb];
                bool takeA = (av > bv) || (av == bv && ai < bi);
                if (takeA) { mv[t] = av; mi[t] = ai; ++pa; }
                else       { mv[t] = bv; mi[t] = bi; ++pb; }
            }
            #pragma unroll
            for (int t = 0; t < NK; ++t) { sv[tid * NK + t] = mv[t]; si[tid * NK + t] = mi[t]; }
        }
        __syncthreads();
    }

    if (tid < NK) {
        out_ids[row * NK + tid]    = (float)si[tid];
        out_scores[row * NK + tid] = sv[tid];
    }
}

// ---------------------------------------------------------------------------
// Launch
// ---------------------------------------------------------------------------
extern "C" void kernel_launch(void* const* d_in, const int* in_sizes, int n_in,
                              void* d_out, int out_size) {
    const int*   ids  = (const int*)d_in[0];
    const float* ctab = (const float*)d_in[1];
    const float* ltab = (const float*)d_in[2];
    const float* W    = (const float*)d_in[3];
    const float* bias = (const float*)d_in[4];

    float* out        = (float*)d_out;
    float* logits     = out;
    float* out_ids    = out + (long)NB * NV;
    float* out_scores = out_ids + NB * NK;

    ctx_kernel<<<NB, ND>>>(ids, ctab, W, bias);

    size_t smem = (size_t)SMEM_HALVES * 2;   // 104448 B
    cudaFuncSetAttribute(gemm_kernel, cudaFuncAttributeMaxDynamicSharedMemorySize, (int)smem);
    dim3 grid(NCG, NRT);
    gemm_kernel<<<grid, 256, smem>>>(ltab, logits);

    topk_kernel<<<NB, TKT>>>(logits, out_ids, out_scores);
}

// round 11
// speedup vs baseline: 2.3540x; 1.5619x over previous
#include <cuda_runtime.h>
#include <cuda_fp16.h>
#include <cstdint>
#include <float.h>

#define NB 2048     // batch
#define NH 50       // history
#define ND 128      // dim (K)
#define NV 100000   // vocab
#define NK 10       // top_k

#define TM 128      // rowtile (batch)
#define TN 64       // coltile (vocab)
#define NCOLT ((NV + TN - 1) / TN)   // 1563
#define NCG 9                        // column groups
#define NRT (NB / TM)                // 16

#define SC   1024.0f                 // fp16 scale (exact power of 2)
#define ISC2 (1.0f / (1024.0f * 1024.0f))

#define HPITCH 136                   // smem pitch in halves (272 B rows: LDSM conflict-free)

// smem (half units): A1 [128][136], A2, B1 [64][136], B2  = 104448 B
#define OFF_A1 0
#define OFF_A2 (TM * HPITCH)
#define OFF_B1 (2 * TM * HPITCH)
#define OFF_B2 (2 * TM * HPITCH + TN * HPITCH)
#define SMEM_HALVES (2 * TM * HPITCH + 2 * TN * HPITCH)

__device__ __align__(16) __half g_a1[NB * ND];
__device__ __align__(16) __half g_a2[NB * ND];
__device__ float g_aux[(long)NB * NCOLT];    // per-(row, coltile) max of logits

// monotonic float<->int key (signed int compare order == float order)
__device__ __forceinline__ int fkey(float f) {
    int u = __float_as_int(f);
    return (u >= 0) ? u : (u ^ 0x7fffffff);
}
__device__ __forceinline__ float ikey(int k) {
    return (k >= 0) ? __int_as_float(k) : __int_as_float(k ^ 0x7fffffff);
}

// m16n8k16 f16 mma, f32 accumulate (sm_80+ base-target instruction)
__device__ __forceinline__ void mma16(float (&d)[4], const uint32_t (&a)[4],
                                      uint32_t b0, uint32_t b1) {
    asm("mma.sync.aligned.m16n8k16.row.col.f32.f16.f16.f32 "
        "{%0,%1,%2,%3}, {%4,%5,%6,%7}, {%8,%9}, {%0,%1,%2,%3};"
        : "+f"(d[0]), "+f"(d[1]), "+f"(d[2]), "+f"(d[3])
        : "r"(a[0]), "r"(a[1]), "r"(a[2]), "r"(a[3]), "r"(b0), "r"(b1));
}

__device__ __forceinline__ void ldsm4(uint32_t (&r)[4], uint32_t addr) {
    asm volatile("ldmatrix.sync.aligned.m8n8.x4.shared.b16 {%0,%1,%2,%3}, [%4];"
        : "=r"(r[0]), "=r"(r[1]), "=r"(r[2]), "=r"(r[3]) : "r"(addr));
}

// split scaled f32 into two fp16 (a ~= h1 + h2, both normal-range after SC scaling)
__device__ __forceinline__ void hsplit(float a, __half& h1, __half& h2) {
    float w = a * SC;
    h1 = __float2half_rn(w);
    h2 = __float2half_rn(w - __half2float(h1));
}

// ---------------------------------------------------------------------------
// Kernel 1: ctx = mean(ctab[ids]) @ W + b, then scaled fp16 hi/lo split
// ---------------------------------------------------------------------------
__global__ void ctx_kernel(const int* __restrict__ ids,
                           const float* __restrict__ ctab,
                           const float* __restrict__ W,
                           const float* __restrict__ bias) {
    int row = blockIdx.x;
    int d = threadIdx.x;
    __shared__ float pooled[ND];

    float s = 0.0f;
    #pragma unroll 5
    for (int h = 0; h < NH; ++h) {
        int id = ids[row * NH + h];
        s += ctab[(long)id * ND + d];
    }
    pooled[d] = s * (1.0f / (float)NH);
    __syncthreads();

    float acc = bias[d];
    #pragma unroll 8
    for (int i = 0; i < ND; ++i)
        acc = fmaf(pooled[i], W[i * ND + d], acc);

    __half h1, h2;
    hsplit(acc, h1, h2);
    g_a1[row * ND + d] = h1;
    g_a2[row * ND + d] = h2;
}

// ---------------------------------------------------------------------------
// Kernel 2: logits = ctx @ labelT via mma.sync 3x FP16 (2-term split, scaled)
// + per-(row, tile) max sideband into g_aux for pruned top-k.
// ---------------------------------------------------------------------------
extern __shared__ __half sm_h[];

__global__ __launch_bounds__(256, 1)
void gemm_kernel(const float* __restrict__ label, float* __restrict__ out) {
    const int tid  = threadIdx.x;
    const int lane = tid & 31;
    const int wid  = tid >> 5;
    const int r0   = blockIdx.y * TM;

    __shared__ int s_rowmax[TM];
    if (tid < TM) s_rowmax[tid] = 0x80000000;   // key-space -inf sentinel

    // ---- Load resident A rowtile (pre-split fp16 a1/a2) ----
    {
        int m  = tid >> 1;
        int d0 = (tid & 1) * 64;
        const uint4* p1 = (const uint4*)(g_a1 + (long)(r0 + m) * ND + d0);
        const uint4* p2 = (const uint4*)(g_a2 + (long)(r0 + m) * ND + d0);
        uint4* d1 = (uint4*)(sm_h + OFF_A1 + m * HPITCH + d0);
        uint4* d2 = (uint4*)(sm_h + OFF_A2 + m * HPITCH + d0);
        #pragma unroll
        for (int j = 0; j < 8; ++j) { d1[j] = p1[j]; d2[j] = p2[j]; }
    }

    // ---- Precompute per-thread ldmatrix base addresses (bytes) ----
    const uint32_t sbase = (uint32_t)__cvta_generic_to_shared(sm_h);
    uint32_t aA1[2], aA2[2], bB1[2], bB2[2];
    {
        int jrowA = ((lane >> 3) & 1) * 8 + (lane & 7);
        int kcolA = (lane >> 4) * 8;
        #pragma unroll
        for (int mi = 0; mi < 2; ++mi) {
            int rowA = (wid >> 1) * 32 + mi * 16 + jrowA;
            aA1[mi] = sbase + (uint32_t)(OFF_A1 + rowA * HPITCH + kcolA) * 2u;
            aA2[mi] = sbase + (uint32_t)(OFF_A2 + rowA * HPITCH + kcolA) * 2u;
        }
        int jrowB = (lane >> 4) * 8 + (lane & 7);
        int kcolB = ((lane >> 3) & 1) * 8;
        #pragma unroll
        for (int p = 0; p < 2; ++p) {
            int rowB = (wid & 1) * 32 + p * 16 + jrowB;
            bB1[p] = sbase + (uint32_t)(OFF_B1 + rowB * HPITCH + kcolB) * 2u;
            bB2[p] = sbase + (uint32_t)(OFF_B2 + rowB * HPITCH + kcolB) * 2u;
        }
    }

    // B prefetch mapping: thread covers vocab-row pn, float-cols pd + 16j
    const int pn = tid >> 2;
    const int pd = (tid & 3) * 4;
    float4 pf[8];
    {
        int gn = blockIdx.x * TN + pn;
        if (gn < NV) {
            const float4* src = (const float4*)(label + (long)gn * ND + pd);
            #pragma unroll
            for (int j = 0; j < 8; ++j) pf[j] = src[j * 4];
        } else {
            #pragma unroll
            for (int j = 0; j < 8; ++j) pf[j] = make_float4(0.f, 0.f, 0.f, 0.f);
        }
    }

    int ct = blockIdx.x;
    while (true) {
        // ---- fill: split prefetched B into fp16 b1/b2 smem ----
        __syncthreads();   // prior tile's frag reads + rowmax reset visible
        {
            __half* b1 = sm_h + OFF_B1 + pn * HPITCH + pd;
            __half* b2 = sm_h + OFF_B2 + pn * HPITCH + pd;
            #pragma unroll
            for (int j = 0; j < 8; ++j) {
                float4 v = pf[j];
                __half hx1, hx2, hy1, hy2, hz1, hz2, hw1, hw2;
                hsplit(v.x, hx1, hx2); hsplit(v.y, hy1, hy2);
                hsplit(v.z, hz1, hz2); hsplit(v.w, hw1, hw2);
                __half2* q1 = (__half2*)(b1 + j * 16);
                __half2* q2 = (__half2*)(b2 + j * 16);
                q1[0] = __halves2half2(hx1, hy1);
                q1[1] = __halves2half2(hz1, hw1);
                q2[0] = __halves2half2(hx2, hy2);
                q2[1] = __halves2half2(hz2, hw2);
            }
        }
        __syncthreads();

        // ---- prefetch next tile into regs (hidden under compute) ----
        const int nct = ct + NCG;
        const bool hasnext = (nct < NCOLT);
        if (hasnext) {
            int gn = nct * TN + pn;
            if (gn < NV) {
                const float4* src = (const float4*)(label + (long)gn * ND + pd);
                #pragma unroll
                for (int j = 0; j < 8; ++j) pf[j] = src[j * 4];
            } else {
                #pragma unroll
                for (int j = 0; j < 8; ++j) pf[j] = make_float4(0.f, 0.f, 0.f, 0.f);
            }
        }

        // ---- compute: register-double-buffered frags, ldmatrix loads ----
        uint32_t A1f[2][2][4], A2f[2][2][4], B1f[2][2][4], B2f[2][2][4];
        float acc[2][4][4];
        #pragma unroll
        for (int mi = 0; mi < 2; ++mi)
            #pragma unroll
            for (int ni = 0; ni < 4; ++ni)
                #pragma unroll
                for (int q = 0; q < 4; ++q) acc[mi][ni][q] = 0.0f;

        ldsm4(A1f[0][0], aA1[0]); ldsm4(A1f[0][1], aA1[1]);
        ldsm4(A2f[0][0], aA2[0]); ldsm4(A2f[0][1], aA2[1]);
        ldsm4(B1f[0][0], bB1[0]); ldsm4(B1f[0][1], bB1[1]);
        ldsm4(B2f[0][0], bB2[0]); ldsm4(B2f[0][1], bB2[1]);

        #pragma unroll
        for (int ks = 0; ks < 8; ++ks) {
            const int cur = ks & 1;
            if (ks < 7) {
                const int nxt = cur ^ 1;
                const uint32_t ko = (uint32_t)(ks + 1) * 32u;
                ldsm4(A1f[nxt][0], aA1[0] + ko); ldsm4(A1f[nxt][1], aA1[1] + ko);
                ldsm4(A2f[nxt][0], aA2[0] + ko); ldsm4(A2f[nxt][1], aA2[1] + ko);
                ldsm4(B1f[nxt][0], bB1[0] + ko); ldsm4(B1f[nxt][1], bB1[1] + ko);
                ldsm4(B2f[nxt][0], bB2[0] + ko); ldsm4(B2f[nxt][1], bB2[1] + ko);
            }
            #pragma unroll
            for (int mi = 0; mi < 2; ++mi)
                #pragma unroll
                for (int p = 0; p < 2; ++p) {
                    mma16(acc[mi][2*p],   A1f[cur][mi], B1f[cur][p][0], B1f[cur][p][1]);
                    mma16(acc[mi][2*p+1], A1f[cur][mi], B1f[cur][p][2], B1f[cur][p][3]);
                    mma16(acc[mi][2*p],   A1f[cur][mi], B2f[cur][p][0], B2f[cur][p][1]);
                    mma16(acc[mi][2*p+1], A1f[cur][mi], B2f[cur][p][2], B2f[cur][p][3]);
                    mma16(acc[mi][2*p],   A2f[cur][mi], B1f[cur][p][0], B1f[cur][p][1]);
                    mma16(acc[mi][2*p+1], A2f[cur][mi], B1f[cur][p][2], B1f[cur][p][3]);
                }
        }

        // ---- epilogue: un-scale (exact 2^-20), store, tile-max sideband ----
        {
            const int n0 = ct * TN;
            #pragma unroll
            for (int mi = 0; mi < 2; ++mi) {
                int rloc0 = (wid >> 1) * 32 + mi * 16 + (lane >> 2);
                long rg = r0 + rloc0;
                float* o0 = out + rg * (long)NV;
                float* o1 = o0 + 8l * NV;
                float m0 = -FLT_MAX, m1 = -FLT_MAX;
                #pragma unroll
                for (int ni = 0; ni < 4; ++ni) {
                    int cg = n0 + (wid & 1) * 32 + ni * 8 + 2 * (lane & 3);
                    float v0 = acc[mi][ni][0] * ISC2, v1 = acc[mi][ni][1] * ISC2;
                    float v2 = acc[mi][ni][2] * ISC2, v3 = acc[mi][ni][3] * ISC2;
                    if (cg < NV) {
                        *(float2*)(o0 + cg) = make_float2(v0, v1);
                        *(float2*)(o1 + cg) = make_float2(v2, v3);
                    }
                    m0 = fmaxf(m0, fmaxf(v0, v1));
                    m1 = fmaxf(m1, fmaxf(v2, v3));
                }
                atomicMax(&s_rowmax[rloc0],     fkey(m0));
                atomicMax(&s_rowmax[rloc0 + 8], fkey(m1));
            }
        }
        __syncthreads();
        if (tid < TM) {
            g_aux[(long)(r0 + tid) * NCOLT + ct] = ikey(s_rowmax[tid]);
            s_rowmax[tid] = 0x80000000;
        }

        if (!hasnext) break;
        ct = nct;
    }
}

// ---------------------------------------------------------------------------
// Kernel 3: pruned per-row top-10 using g_aux tile maxima.
// Scan tiles in descending max order; stop when best remaining max < 10th value.
// ---------------------------------------------------------------------------
#define T2 256

__global__ __launch_bounds__(T2)
void topk_kernel(const float* __restrict__ logits,
                 float* __restrict__ out_ids,
                 float* __restrict__ out_scores) {
    const int row = blockIdx.x;
    const int tid = threadIdx.x;

    __shared__ float sm[NCOLT];
    __shared__ float rv[T2];
    __shared__ int   ri[T2];
    __shared__ float tv[NK];
    __shared__ int   ti[NK];
    __shared__ float cand[TN];

    for (int j = tid; j < NCOLT; j += T2)
        sm[j] = g_aux[(long)row * NCOLT + j];
    if (tid < NK) { tv[tid] = -FLT_MAX; ti[tid] = 0; }
    __syncthreads();

    const float* lrow = logits + (long)row * NV;

    for (int round = 0; round < NCOLT; ++round) {
        // parallel argmax over remaining tile maxima (tie -> smaller idx)
        float bv = -FLT_MAX; int bi = NCOLT;
        for (int j = tid; j < NCOLT; j += T2) {
            float v = sm[j];
            if (v > bv || (v == bv && j < bi)) { bv = v; bi = j; }
        }
        rv[tid] = bv; ri[tid] = bi;
        __syncthreads();
        #pragma unroll
        for (int s = T2 / 2; s > 0; s >>= 1) {
            if (tid < s) {
                float ov = rv[tid + s]; int oi = ri[tid + s];
                if (ov > rv[tid] || (ov == rv[tid] && oi < ri[tid])) {
                    rv[tid] = ov; ri[tid] = oi;
                }
            }
            __syncthreads();
        }
        float best = rv[0]; int bidx = ri[0];
        if (best < tv[NK - 1] || bidx >= NCOLT) break;   // strict <: equal still scanned

        // scan tile bidx (64 logits)
        if (tid < TN) {
            int c = bidx * TN + tid;
            cand[tid] = (c < NV) ? lrow[c] : -FLT_MAX;
        }
        __syncthreads();
        if (tid == 0) {
            #pragma unroll 4
            for (int c = 0; c < TN; ++c) {
                float v = cand[c];
                int   id = bidx * TN + c;
                if (v > tv[NK - 1] || (v == tv[NK - 1] && v > -FLT_MAX && id < ti[NK - 1])) {
                    tv[NK - 1] = v; ti[NK - 1] = id;
                    #pragma unroll
                    for (int j = NK - 1; j > 0; --j) {
                        bool sw = (tv[j] > tv[j - 1]) ||
                                  (tv[j] == tv[j - 1] && ti[j] < ti[j - 1]);
                        if (sw) {
                            float fv = tv[j]; tv[j] = tv[j - 1]; tv[j - 1] = fv;
                            int ii = ti[j]; ti[j] = ti[j - 1]; ti[j - 1] = ii;
                        }
                    }
                }
            }
            sm[bidx] = -FLT_MAX;
        }
        __syncthreads();
    }

    if (tid < NK) {
        out_ids[row * NK + tid]    = (float)ti[tid];
        out_scores[row * NK + tid] = tv[tid];
    }
}

// ---------------------------------------------------------------------------
// Launch
// ---------------------------------------------------------------------------
extern "C" void kernel_launch(void* const* d_in, const int* in_sizes, int n_in,
                              void* d_out, int out_size) {
    const int*   ids  = (const int*)d_in[0];
    const float* ctab = (const float*)d_in[1];
    const float* ltab = (const float*)d_in[2];
    const float* W    = (const float*)d_in[3];
    const float* bias = (const float*)d_in[4];

    float* out        = (float*)d_out;
    float* logits     = out;
    float* out_ids    = out + (long)NB * NV;
    float* out_scores = out_ids + NB * NK;

    ctx_kernel<<<NB, ND>>>(ids, ctab, W, bias);

    size_t smem = (size_t)SMEM_HALVES * 2;   // 104448 B
    cudaFuncSetAttribute(gemm_kernel, cudaFuncAttributeMaxDynamicSharedMemorySize, (int)smem);
    dim3 grid(NCG, NRT);
    gemm_kernel<<<grid, 256, smem>>>(ltab, logits);

    topk_kernel<<<NB, T2>>>(logits, out_ids, out_scores);
}

// round 12
// speedup vs baseline: 2.5325x; 1.0758x over previous
#include <cuda_runtime.h>
#include <cuda_fp16.h>
#include <cstdint>
#include <float.h>

#define NB 2048     // batch
#define NH 50       // history
#define ND 128      // dim (K)
#define NV 100000   // vocab
#define NK 10       // top_k

#define TM 256      // rowtile (batch)
#define TN 64       // coltile (vocab)
#define NCOLT ((NV + TN - 1) / TN)   // 1563
#define NCG 18                       // column groups
#define NRT (NB / TM)                // 8   -> 144 CTAs

#define SC   1024.0f                 // fp16 scale (exact power of 2)
#define ISC2 (1.0f / (1024.0f * 1024.0f))

#define HPITCH 136                   // smem pitch in halves (272 B rows: LDSM conflict-free)

// smem (half units): A1 [256][136], A2, B1 [64][136], B2  = 174080 B
#define OFF_A1 0
#define OFF_A2 (TM * HPITCH)
#define OFF_B1 (2 * TM * HPITCH)
#define OFF_B2 (2 * TM * HPITCH + TN * HPITCH)
#define SMEM_HALVES (2 * TM * HPITCH + 2 * TN * HPITCH)

__device__ __align__(16) __half g_a1[NB * ND];
__device__ __align__(16) __half g_a2[NB * ND];
__device__ float g_aux[(long)NB * NCOLT];    // per-(row, coltile) max of logits

// monotonic float<->int key (signed int compare order == float order)
__device__ __forceinline__ int fkey(float f) {
    int u = __float_as_int(f);
    return (u >= 0) ? u : (u ^ 0x7fffffff);
}
__device__ __forceinline__ float ikey(int k) {
    return (k >= 0) ? __int_as_float(k) : __int_as_float(k ^ 0x7fffffff);
}

// m16n8k16 f16 mma, f32 accumulate (sm_80+ base-target instruction)
__device__ __forceinline__ void mma16(float (&d)[4], const uint32_t (&a)[4],
                                      uint32_t b0, uint32_t b1) {
    asm("mma.sync.aligned.m16n8k16.row.col.f32.f16.f16.f32 "
        "{%0,%1,%2,%3}, {%4,%5,%6,%7}, {%8,%9}, {%0,%1,%2,%3};"
        : "+f"(d[0]), "+f"(d[1]), "+f"(d[2]), "+f"(d[3])
        : "r"(a[0]), "r"(a[1]), "r"(a[2]), "r"(a[3]), "r"(b0), "r"(b1));
}

__device__ __forceinline__ void ldsm4(uint32_t (&r)[4], uint32_t addr) {
    asm volatile("ldmatrix.sync.aligned.m8n8.x4.shared.b16 {%0,%1,%2,%3}, [%4];"
        : "=r"(r[0]), "=r"(r[1]), "=r"(r[2]), "=r"(r[3]) : "r"(addr));
}

// split scaled f32 into two fp16 (a ~= h1 + h2, both normal-range after SC scaling)
__device__ __forceinline__ void hsplit(float a, __half& h1, __half& h2) {
    float w = a * SC;
    h1 = __float2half_rn(w);
    h2 = __float2half_rn(w - __half2float(h1));
}

// ---------------------------------------------------------------------------
// Kernel 1: ctx = mean(ctab[ids]) @ W + b, then scaled fp16 hi/lo split
// ---------------------------------------------------------------------------
__global__ void ctx_kernel(const int* __restrict__ ids,
                           const float* __restrict__ ctab,
                           const float* __restrict__ W,
                           const float* __restrict__ bias) {
    int row = blockIdx.x;
    int d = threadIdx.x;
    __shared__ float pooled[ND];

    float s = 0.0f;
    #pragma unroll 5
    for (int h = 0; h < NH; ++h) {
        int id = ids[row * NH + h];
        s += ctab[(long)id * ND + d];
    }
    pooled[d] = s * (1.0f / (float)NH);
    __syncthreads();

    float acc = bias[d];
    #pragma unroll 8
    for (int i = 0; i < ND; ++i)
        acc = fmaf(pooled[i], W[i * ND + d], acc);

    __half h1, h2;
    hsplit(acc, h1, h2);
    g_a1[row * ND + d] = h1;
    g_a2[row * ND + d] = h2;
}

// ---------------------------------------------------------------------------
// Kernel 2: logits = ctx @ labelT via mma.sync 3x FP16 (2-term split, scaled)
// TM=256 rowtile: warp tile 64x32, B fill/overheads amortized 2x per output.
// + per-(row, tile) max sideband into g_aux for pruned top-k.
// ---------------------------------------------------------------------------
extern __shared__ __half sm_h[];

__global__ __launch_bounds__(256, 1)
void gemm_kernel(const float* __restrict__ label, float* __restrict__ out) {
    const int tid  = threadIdx.x;
    const int lane = tid & 31;
    const int wid  = tid >> 5;
    const int r0   = blockIdx.y * TM;

    __shared__ int s_rowmax[TM];
    s_rowmax[tid] = 0x80000000;   // key-space -inf sentinel (256 threads, TM=256)

    // ---- Load resident A rowtile (pre-split fp16 a1/a2): one row per thread ----
    {
        const uint4* p1 = (const uint4*)(g_a1 + (long)(r0 + tid) * ND);
        const uint4* p2 = (const uint4*)(g_a2 + (long)(r0 + tid) * ND);
        uint4* d1 = (uint4*)(sm_h + OFF_A1 + tid * HPITCH);
        uint4* d2 = (uint4*)(sm_h + OFF_A2 + tid * HPITCH);
        #pragma unroll
        for (int j = 0; j < 16; ++j) { d1[j] = p1[j]; d2[j] = p2[j]; }
    }

    // ---- Precompute per-thread ldmatrix base addresses (bytes) ----
    const uint32_t sbase = (uint32_t)__cvta_generic_to_shared(sm_h);
    uint32_t aA1[4], aA2[4], bB1[2], bB2[2];
    {
        int jrowA = ((lane >> 3) & 1) * 8 + (lane & 7);
        int kcolA = (lane >> 4) * 8;
        #pragma unroll
        for (int mi = 0; mi < 4; ++mi) {
            int rowA = (wid >> 1) * 64 + mi * 16 + jrowA;
            aA1[mi] = sbase + (uint32_t)(OFF_A1 + rowA * HPITCH + kcolA) * 2u;
            aA2[mi] = sbase + (uint32_t)(OFF_A2 + rowA * HPITCH + kcolA) * 2u;
        }
        int jrowB = (lane >> 4) * 8 + (lane & 7);
        int kcolB = ((lane >> 3) & 1) * 8;
        #pragma unroll
        for (int p = 0; p < 2; ++p) {
            int rowB = (wid & 1) * 32 + p * 16 + jrowB;
            bB1[p] = sbase + (uint32_t)(OFF_B1 + rowB * HPITCH + kcolB) * 2u;
            bB2[p] = sbase + (uint32_t)(OFF_B2 + rowB * HPITCH + kcolB) * 2u;
        }
    }

    // B prefetch mapping: thread covers vocab-row pn, float-cols pd + 16j
    const int pn = tid >> 2;
    const int pd = (tid & 3) * 4;
    float4 pf[8];
    {
        int gn = blockIdx.x * TN + pn;
        if (gn < NV) {
            const float4* src = (const float4*)(label + (long)gn * ND + pd);
            #pragma unroll
            for (int j = 0; j < 8; ++j) pf[j] = src[j * 4];
        } else {
            #pragma unroll
            for (int j = 0; j < 8; ++j) pf[j] = make_float4(0.f, 0.f, 0.f, 0.f);
        }
    }

    int ct = blockIdx.x;
    while (true) {
        // ---- fill: split prefetched B into fp16 b1/b2 smem ----
        __syncthreads();   // prior tile's frag reads + rowmax reset visible
        {
            __half* b1 = sm_h + OFF_B1 + pn * HPITCH + pd;
            __half* b2 = sm_h + OFF_B2 + pn * HPITCH + pd;
            #pragma unroll
            for (int j = 0; j < 8; ++j) {
                float4 v = pf[j];
                __half hx1, hx2, hy1, hy2, hz1, hz2, hw1, hw2;
                hsplit(v.x, hx1, hx2); hsplit(v.y, hy1, hy2);
                hsplit(v.z, hz1, hz2); hsplit(v.w, hw1, hw2);
                __half2* q1 = (__half2*)(b1 + j * 16);
                __half2* q2 = (__half2*)(b2 + j * 16);
                q1[0] = __halves2half2(hx1, hy1);
                q1[1] = __halves2half2(hz1, hw1);
                q2[0] = __halves2half2(hx2, hy2);
                q2[1] = __halves2half2(hz2, hw2);
            }
        }
        __syncthreads();

        // ---- prefetch next tile into regs (hidden under compute) ----
        const int nct = ct + NCG;
        const bool hasnext = (nct < NCOLT);
        if (hasnext) {
            int gn = nct * TN + pn;
            if (gn < NV) {
                const float4* src = (const float4*)(label + (long)gn * ND + pd);
                #pragma unroll
                for (int j = 0; j < 8; ++j) pf[j] = src[j * 4];
            } else {
                #pragma unroll
                for (int j = 0; j < 8; ++j) pf[j] = make_float4(0.f, 0.f, 0.f, 0.f);
            }
        }

        // ---- compute: register-double-buffered frags, ldmatrix loads ----
        uint32_t A1f[2][4][4], A2f[2][4][4], B1f[2][2][4], B2f[2][2][4];
        float acc[4][4][4];
        #pragma unroll
        for (int mi = 0; mi < 4; ++mi)
            #pragma unroll
            for (int ni = 0; ni < 4; ++ni)
                #pragma unroll
                for (int q = 0; q < 4; ++q) acc[mi][ni][q] = 0.0f;

        #pragma unroll
        for (int mi = 0; mi < 4; ++mi) { ldsm4(A1f[0][mi], aA1[mi]); ldsm4(A2f[0][mi], aA2[mi]); }
        ldsm4(B1f[0][0], bB1[0]); ldsm4(B1f[0][1], bB1[1]);
        ldsm4(B2f[0][0], bB2[0]); ldsm4(B2f[0][1], bB2[1]);

        #pragma unroll
        for (int ks = 0; ks < 8; ++ks) {
            const int cur = ks & 1;
            if (ks < 7) {
                const int nxt = cur ^ 1;
                const uint32_t ko = (uint32_t)(ks + 1) * 32u;   // 16 halves = 32 B
                #pragma unroll
                for (int mi = 0; mi < 4; ++mi) {
                    ldsm4(A1f[nxt][mi], aA1[mi] + ko);
                    ldsm4(A2f[nxt][mi], aA2[mi] + ko);
                }
                ldsm4(B1f[nxt][0], bB1[0] + ko); ldsm4(B1f[nxt][1], bB1[1] + ko);
                ldsm4(B2f[nxt][0], bB2[0] + ko); ldsm4(B2f[nxt][1], bB2[1] + ko);
            }
            #pragma unroll
            for (int mi = 0; mi < 4; ++mi)
                #pragma unroll
                for (int p = 0; p < 2; ++p) {
                    mma16(acc[mi][2*p],   A1f[cur][mi], B1f[cur][p][0], B1f[cur][p][1]);
                    mma16(acc[mi][2*p+1], A1f[cur][mi], B1f[cur][p][2], B1f[cur][p][3]);
                    mma16(acc[mi][2*p],   A1f[cur][mi], B2f[cur][p][0], B2f[cur][p][1]);
                    mma16(acc[mi][2*p+1], A1f[cur][mi], B2f[cur][p][2], B2f[cur][p][3]);
                    mma16(acc[mi][2*p],   A2f[cur][mi], B1f[cur][p][0], B1f[cur][p][1]);
                    mma16(acc[mi][2*p+1], A2f[cur][mi], B1f[cur][p][2], B1f[cur][p][3]);
                }
        }

        // ---- epilogue: un-scale (exact 2^-20), store, tile-max sideband ----
        {
            const int n0 = ct * TN;
            #pragma unroll
            for (int mi = 0; mi < 4; ++mi) {
                int rloc0 = (wid >> 1) * 64 + mi * 16 + (lane >> 2);
                long rg = r0 + rloc0;
                float* o0 = out + rg * (long)NV;
                float* o1 = o0 + 8l * NV;
                float m0 = -FLT_MAX, m1 = -FLT_MAX;
                #pragma unroll
                for (int ni = 0; ni < 4; ++ni) {
                    int cg = n0 + (wid & 1) * 32 + ni * 8 + 2 * (lane & 3);
                    float v0 = acc[mi][ni][0] * ISC2, v1 = acc[mi][ni][1] * ISC2;
                    float v2 = acc[mi][ni][2] * ISC2, v3 = acc[mi][ni][3] * ISC2;
                    if (cg < NV) {
                        *(float2*)(o0 + cg) = make_float2(v0, v1);
                        *(float2*)(o1 + cg) = make_float2(v2, v3);
                    }
                    m0 = fmaxf(m0, fmaxf(v0, v1));
                    m1 = fmaxf(m1, fmaxf(v2, v3));
                }
                atomicMax(&s_rowmax[rloc0],     fkey(m0));
                atomicMax(&s_rowmax[rloc0 + 8], fkey(m1));
            }
        }
        __syncthreads();
        {
            g_aux[(long)(r0 + tid) * NCOLT + ct] = ikey(s_rowmax[tid]);
            s_rowmax[tid] = 0x80000000;
        }

        if (!hasnext) break;
        ct = nct;
    }
}

// ---------------------------------------------------------------------------
// Kernel 3: pruned per-row top-10 using g_aux tile maxima.
// ---------------------------------------------------------------------------
#define T2 256

__global__ __launch_bounds__(T2)
void topk_kernel(const float* __restrict__ logits,
                 float* __restrict__ out_ids,
                 float* __restrict__ out_scores) {
    const int row = blockIdx.x;
    const int tid = threadIdx.x;

    __shared__ float sm[NCOLT];
    __shared__ float rv[T2];
    __shared__ int   ri[T2];
    __shared__ float tv[NK];
    __shared__ int   ti[NK];
    __shared__ float cand[TN];

    for (int j = tid; j < NCOLT; j += T2)
        sm[j] = g_aux[(long)row * NCOLT + j];
    if (tid < NK) { tv[tid] = -FLT_MAX; ti[tid] = 0; }
    __syncthreads();

    const float* lrow = logits + (long)row * NV;

    for (int round = 0; round < NCOLT; ++round) {
        float bv = -FLT_MAX; int bi = NCOLT;
        for (int j = tid; j < NCOLT; j += T2) {
            float v = sm[j];
            if (v > bv || (v == bv && j < bi)) { bv = v; bi = j; }
        }
        rv[tid] = bv; ri[tid] = bi;
        __syncthreads();
        #pragma unroll
        for (int s = T2 / 2; s > 0; s >>= 1) {
            if (tid < s) {
                float ov = rv[tid + s]; int oi = ri[tid + s];
                if (ov > rv[tid] || (ov == rv[tid] && oi < ri[tid])) {
                    rv[tid] = ov; ri[tid] = oi;
                }
            }
            __syncthreads();
        }
        float best = rv[0]; int bidx = ri[0];
        if (best < tv[NK - 1] || bidx >= NCOLT) break;

        if (tid < TN) {
            int c = bidx * TN + tid;
            cand[tid] = (c < NV) ? lrow[c] : -FLT_MAX;
        }
        __syncthreads();
        if (tid == 0) {
            #pragma unroll 4
            for (int c = 0; c < TN; ++c) {
                float v = cand[c];
                int   id = bidx * TN + c;
                if (v > tv[NK - 1] || (v == tv[NK - 1] && v > -FLT_MAX && id < ti[NK - 1])) {
                    tv[NK - 1] = v; ti[NK - 1] = id;
                    #pragma unroll
                    for (int j = NK - 1; j > 0; --j) {
                        bool sw = (tv[j] > tv[j - 1]) ||
                                  (tv[j] == tv[j - 1] && ti[j] < ti[j - 1]);
                        if (sw) {
                            float fv = tv[j]; tv[j] = tv[j - 1]; tv[j - 1] = fv;
                            int ii = ti[j]; ti[j] = ti[j - 1]; ti[j - 1] = ii;
                        }
                    }
                }
            }
            sm[bidx] = -FLT_MAX;
        }
        __syncthreads();
    }

    if (tid < NK) {
        out_ids[row * NK + tid]    = (float)ti[tid];
        out_scores[row * NK + tid] = tv[tid];
    }
}

// ---------------------------------------------------------------------------
// Launch
// ---------------------------------------------------------------------------
extern "C" void kernel_launch(void* const* d_in, const int* in_sizes, int n_in,
                              void* d_out, int out_size) {
    const int*   ids  = (const int*)d_in[0];
    const float* ctab = (const float*)d_in[1];
    const float* ltab = (const float*)d_in[2];
    const float* W    = (const float*)d_in[3];
    const float* bias = (const float*)d_in[4];

    float* out        = (float*)d_out;
    float* logits     = out;
    float* out_ids    = out + (long)NB * NV;
    float* out_scores = out_ids + NB * NK;

    ctx_kernel<<<NB, ND>>>(ids, ctab, W, bias);

    size_t smem = (size_t)SMEM_HALVES * 2;   // 174080 B
    cudaFuncSetAttribute(gemm_kernel, cudaFuncAttributeMaxDynamicSharedMemorySize, (int)smem);
    dim3 grid(NCG, NRT);
    gemm_kernel<<<grid, 256, smem>>>(ltab, logits);

    topk_kernel<<<NB, T2>>>(logits, out_ids, out_scores);
}